// round 14
// baseline (speedup 1.0000x reference)
#include <cuda_runtime.h>
#include <cstdint>

// C51 categorical projection, round 14 (closing probe).
// R7's best-measured tile size (13 KB, ROWS=64/THREADS=128) combined with
// R13's double buffering: both TMA loads issued at block start, tile 1's load
// hides behind tile 0's compute, tile 0's store drains behind tile 1.
// Merge core unchanged (2 threads/row, predicated streaming merge, in-place).

static constexpr int ATOMS_C    = 51;
static constexpr int ROWS       = 64;               // rows per tile
static constexpr int THREADS    = 128;              // 2 threads per row
static constexpr int TILE       = ROWS * ATOMS_C;   // 3264 floats
static constexpr int TILE_BYTES = TILE * 4;         // 13056
static constexpr int HALFN      = 26;               // atoms per half (incl. dummy)
static constexpr int NT         = 2;                // tiles per block
static constexpr int V4         = TILE / 4;         // 816
static constexpr int V4FULL     = (V4 / THREADS) * THREADS;  // 768
static constexpr int V4REM      = V4 - V4FULL;               // 48

__global__ __launch_bounds__(THREADS) void c51_project_kernel(
    const float* __restrict__ g_reward,
    const float* __restrict__ g_dist,
    const int*   __restrict__ g_mask,
    float*       __restrict__ g_out)
{
    __shared__ alignas(128) float s_tile[NT][TILE];
    __shared__ alignas(8)  unsigned long long s_mbar[NT];

    const int tid  = threadIdx.x;
    const int row  = tid & (ROWS - 1);
    const int half = tid >> 6;                      // 0: atoms 0..25, 1: 25..50

    uint32_t u_tile[NT], u_mbar[NT];
    #pragma unroll
    for (int p = 0; p < NT; ++p) {
        u_tile[p] = (uint32_t)__cvta_generic_to_shared(s_tile[p]);
        u_mbar[p] = (uint32_t)__cvta_generic_to_shared(&s_mbar[p]);
    }

    // ---- init barriers, then issue BOTH loads immediately ----
    if (tid == 0) {
        #pragma unroll
        for (int p = 0; p < NT; ++p)
            asm volatile("mbarrier.init.shared::cta.b64 [%0], 1;" :: "r"(u_mbar[p]));
        asm volatile("fence.proxy.async.shared::cta;" ::: "memory");
    }
    __syncthreads();
    if (tid == 0) {
        #pragma unroll
        for (int p = 0; p < NT; ++p) {
            const long long tg = ((long long)blockIdx.x * NT + p) * TILE;
            asm volatile("mbarrier.arrive.expect_tx.shared::cta.b64 _, [%0], %1;"
                         :: "r"(u_mbar[p]), "r"(TILE_BYTES) : "memory");
            asm volatile(
                "cp.async.bulk.shared::cta.global.mbarrier::complete_tx::bytes "
                "[%0], [%1], %2, [%3];"
                :: "r"(u_tile[p]), "l"(g_dist + tg), "r"(TILE_BYTES),
                   "r"(u_mbar[p]) : "memory");
        }
    }

    const float HI = 49.999996f;                    // largest f32 < 50

    #pragma unroll
    for (int p = 0; p < NT; ++p) {
        const int       t      = blockIdx.x * NT + p;
        const long long base_g = (long long)t * TILE;

        // ---- per-row affine bin map (overlaps the load wait) ----
        const int   r    = t * ROWS + row;
        const float rw   = __ldg(g_reward + r);
        const float mk   = (float)__ldg(g_mask + r);
        const float step = 0.99f * mk;
        float base = (rw + 10.0f) / 0.4f - 24.75f * mk;   // one div per row
        base = fmaf(step, (float)(half * 25), base);       // shift to atom 25*half

        // ---- wait for this tile (parity 0; each barrier used once) ----
        {
            uint32_t done;
            asm volatile(
                "{\n\t.reg .pred q;\n\t"
                "mbarrier.try_wait.parity.shared::cta.b64 q, [%1], 0;\n\t"
                "selp.b32 %0, 1, 0, q;\n\t}"
                : "=r"(done) : "r"(u_mbar[p]) : "memory");
            while (!done) {
                asm volatile(
                    "{\n\t.reg .pred q;\n\t"
                    "mbarrier.try_wait.parity.shared::cta.b64 q, [%1], 0, 0x989680;\n\t"
                    "selp.b32 %0, 1, 0, q;\n\t}"
                    : "=r"(done) : "r"(u_mbar[p]) : "memory");
            }
        }

        float* __restrict__ tile = s_tile[p];

        // ---- buffer own half-row into registers (stride 51, conflict-free) ----
        float d[HALFN];
        {
            const float* __restrict__ srow = tile + row * ATOMS_C + half * 25;
            #pragma unroll
            for (int j = 0; j < HALFN; ++j) d[j] = srow[j];
            if (half) d[0] = 0.0f;                 // dummy atom 25: zero weight
        }
        __syncthreads();                           // all reads before overwrite

        // ---- cooperative zero of the tile (reused in-place as output) ----
        float4* s4 = reinterpret_cast<float4*>(tile);
        const float4 z4 = make_float4(0.f, 0.f, 0.f, 0.f);
        #pragma unroll
        for (int i = 0; i < V4FULL / THREADS; ++i)
            s4[i * THREADS + tid] = z4;
        if (tid < V4REM) s4[V4FULL + tid] = z4;
        __syncthreads();

        // ---- streaming merge over this thread's 26 atoms ----
        float* __restrict__ orow = tile + row * ATOMS_C;

        float b    = fminf(fmaxf(base, 0.0f), HI);
        float curf = floorf(b);
        float* wptr = orow + (int)curf;            // single F2I per thread
        float acc1 = d[0] * (b - curf);            // half==1: d[0]=0 -> accs 0
        float acc0 = d[0] - acc1;

        #pragma unroll
        for (int j = 1; j < HALFN; ++j) {
            float bb = fmaf(step, (float)j, base); // FFMA, imm multiplier
            bb = fminf(fmaxf(bb, 0.0f), HI);
            const float lfn = floorf(bb);          // independent per atom
            const float bm  = bb - lfn;
            const float wu  = d[j] * bm;
            const float wl  = d[j] - wu;           // d*(lf+1-b)
            const bool adv  = (lfn != curf);       // l steps by exactly 0/1
            if (adv) *wptr = acc0;                 // @P STS, converged
            const float a0 = adv ? acc1 : acc0;
            acc0 = a0 + wl;
            const float tt = acc1 + wu;
            acc1 = adv ? wu : tt;
            wptr = adv ? (wptr + 1) : wptr;
            curf = lfn;
        }
        if (half) {                                // B: plain final flush
            wptr[0] = acc0;                        // covers [cA, cB+1] once
            wptr[1] = acc1;
        }
        __syncthreads();
        if (!half) {                               // A: deferred carry, RMW add
            wptr[0] += acc0;                       // bins [cA, cA+1], B's region
            wptr[1] += acc1;
        }

        // ---- bulk store (drains behind the next tile's compute) ----
        asm volatile("fence.proxy.async.shared::cta;" ::: "memory");
        __syncthreads();
        if (tid == 0) {
            asm volatile(
                "cp.async.bulk.global.shared::cta.bulk_group [%0], [%1], %2;"
                :: "l"(g_out + base_g), "r"(u_tile[p]), "r"(TILE_BYTES)
                : "memory");
            asm volatile("cp.async.bulk.commit_group;" ::: "memory");
        }
    }
    if (tid == 0)
        asm volatile("cp.async.bulk.wait_group 0;" ::: "memory");
}

extern "C" void kernel_launch(void* const* d_in, const int* in_sizes, int n_in,
                              void* d_out, int out_size) {
    const float* reward = (const float*)d_in[0];   // batch_reward  [B] f32
    const float* dist   = (const float*)d_in[1];   // max_next_dist [B,51] f32
    // d_in[2] = supports (linspace) — folded into the affine map, unused
    const int*   mask   = (const int*)d_in[3];     // non_final_mask[B] i32
    float* out = (float*)d_out;                    // [B,51] f32

    const int B = in_sizes[0];                     // 1048576
    const int blocks = B / (ROWS * NT);            // 8192
    c51_project_kernel<<<blocks, THREADS>>>(reward, dist, mask, out);
}

// round 15
// speedup vs baseline: 1.0061x; 1.0061x over previous
#include <cuda_runtime.h>
#include <cstdint>

// C51 categorical projection — FINAL (round-7 design, best measured: 68.06us,
// DRAM 78.8%, ~6.26 TB/s ~= the mixed 1:1 read:write HBM ceiling).
//
// Design summary (what mattered, in order of impact):
//  1. Row-local scatter -> monotone streaming two-accumulator merge: bin index
//     l(a) is non-decreasing with step {0,1} (bin stride 0.99 < 1), so the
//     scatter becomes a fully predicated register merge — no atomics, no
//     divergence (302 -> 139us).
//  2. Affine bin map b(a) = clamp(step*a + base, 0, 50-eps): clip commutes
//     with the affine map, killing the per-atom division and supports load;
//     exact-integer disambiguation is value-irrelevant (139 -> 94us).
//  3. Single in-place SMEM tile + register row buffer (94 -> 70us).
//  4. TMA bulk stage-in/out: GMEM<->SMEM without LDG/STS/LDS/STG register
//     round-trips, dropping L1tex from 82% to 50% (-> 68.1us wall).
// Rounds 8-14 established the remaining gap is the HBM read/write-turnaround
// ceiling, invariant to occupancy, overlap depth, tile size, and CTA count.

static constexpr int ATOMS_C    = 51;
static constexpr int ROWS       = 64;               // rows per block
static constexpr int THREADS    = 128;              // 2 threads per row
static constexpr int TILE       = ROWS * ATOMS_C;   // 3264 floats
static constexpr int TILE_BYTES = TILE * 4;         // 13056 (multiple of 16)
static constexpr int HALFN      = 26;               // atoms per half (incl. dummy)

__global__ __launch_bounds__(THREADS) void c51_project_kernel(
    const float* __restrict__ g_reward,
    const float* __restrict__ g_dist,
    const int*   __restrict__ g_mask,
    float*       __restrict__ g_out)
{
    __shared__ alignas(128) float s_tile[TILE];
    __shared__ alignas(8)  unsigned long long s_mbar;

    const int tid  = threadIdx.x;
    const int row  = tid & (ROWS - 1);
    const int half = tid >> 6;                      // 0: atoms 0..25, 1: 25..50
    const long long base_g = (long long)blockIdx.x * TILE;

    const uint32_t u_tile = (uint32_t)__cvta_generic_to_shared(s_tile);
    const uint32_t u_mbar = (uint32_t)__cvta_generic_to_shared(&s_mbar);

    // ---- TMA bulk load: GMEM -> SMEM, no register round-trip ----
    if (tid == 0) {
        asm volatile("mbarrier.init.shared::cta.b64 [%0], 1;" :: "r"(u_mbar));
        asm volatile("fence.proxy.async.shared::cta;" ::: "memory");
    }
    __syncthreads();
    if (tid == 0) {
        asm volatile("mbarrier.arrive.expect_tx.shared::cta.b64 _, [%0], %1;"
                     :: "r"(u_mbar), "r"(TILE_BYTES) : "memory");
        asm volatile(
            "cp.async.bulk.shared::cta.global.mbarrier::complete_tx::bytes "
            "[%0], [%1], %2, [%3];"
            :: "r"(u_tile), "l"(g_dist + base_g), "r"(TILE_BYTES), "r"(u_mbar)
            : "memory");
    }

    // ---- Overlap with TMA: per-row affine bin map ----
    const int   r    = blockIdx.x * ROWS + row;
    const float rw   = __ldg(g_reward + r);
    const float mk   = (float)__ldg(g_mask + r);
    const float step = 0.99f * mk;
    float base = (rw + 10.0f) / 0.4f - 24.75f * mk;       // one div per row
    base = fmaf(step, (float)(half * 25), base);           // shift to atom 25*half
    const float HI = 49.999996f;                           // largest f32 < 50

    // ---- Wait for the tile (parity 0) ----
    {
        uint32_t done;
        asm volatile(
            "{\n\t.reg .pred p;\n\t"
            "mbarrier.try_wait.parity.shared::cta.b64 p, [%1], 0;\n\t"
            "selp.b32 %0, 1, 0, p;\n\t}"
            : "=r"(done) : "r"(u_mbar) : "memory");
        while (!done) {
            asm volatile(
                "{\n\t.reg .pred p;\n\t"
                "mbarrier.try_wait.parity.shared::cta.b64 p, [%1], 0, 0x989680;\n\t"
                "selp.b32 %0, 1, 0, p;\n\t}"
                : "=r"(done) : "r"(u_mbar) : "memory");
        }
    }

    // ---- Buffer own half-row into registers (conflict-free, stride 51) ----
    float d[HALFN];
    {
        const float* __restrict__ srow = s_tile + row * ATOMS_C + half * 25;
        #pragma unroll
        for (int j = 0; j < HALFN; ++j) d[j] = srow[j];
        if (half) d[0] = 0.0f;                     // dummy atom 25: zero weight
    }
    __syncthreads();                               // all reads before overwrite

    // ---- Cooperative zero of the tile (reused in-place as output) ----
    float4* s4 = reinterpret_cast<float4*>(s_tile);
    const float4 z4 = make_float4(0.f, 0.f, 0.f, 0.f);
    #pragma unroll
    for (int i = 0; i < (TILE / 4) / THREADS; ++i)      // 6 rounds of 128
        s4[i * THREADS + tid] = z4;
    {   // remainder: 816 = 6*128 + 48
        if (tid < 48) s4[6 * THREADS + tid] = z4;
    }
    __syncthreads();

    // ---- Streaming merge over this thread's 26 atoms ----
    float* __restrict__ orow = s_tile + row * ATOMS_C;

    float b    = fminf(fmaxf(base, 0.0f), HI);
    float curf = floorf(b);
    float* wptr = orow + (int)curf;                // single F2I per thread
    float acc1 = d[0] * (b - curf);                // half==1: d[0]=0 -> accs 0
    float acc0 = d[0] - acc1;

    #pragma unroll
    for (int j = 1; j < HALFN; ++j) {
        float bb = fmaf(step, (float)j, base);     // FFMA, imm multiplier
        bb = fminf(fmaxf(bb, 0.0f), HI);
        const float lfn = floorf(bb);              // independent per atom
        const float bm  = bb - lfn;
        const float wu  = d[j] * bm;
        const float wl  = d[j] - wu;               // d*(lf+1-b)
        const bool adv  = (lfn != curf);           // l steps by exactly 0/1
        if (adv) *wptr = acc0;                     // @P STS, converged
        const float a0 = adv ? acc1 : acc0;
        acc0 = a0 + wl;
        const float t  = acc1 + wu;
        acc1 = adv ? wu : t;
        wptr = adv ? (wptr + 1) : wptr;
        curf = lfn;
    }
    if (half) {                                    // B: plain final flush
        wptr[0] = acc0;                            // covers [cA, cB+1] once
        wptr[1] = acc1;
    }
    __syncthreads();
    if (!half) {                                   // A: deferred carry, RMW add
        wptr[0] += acc0;                           // bins [cA, cA+1], B's region
        wptr[1] += acc1;
    }

    // ---- TMA bulk store: SMEM -> GMEM ----
    asm volatile("fence.proxy.async.shared::cta;" ::: "memory");
    __syncthreads();
    if (tid == 0) {
        asm volatile(
            "cp.async.bulk.global.shared::cta.bulk_group [%0], [%1], %2;"
            :: "l"(g_out + base_g), "r"(u_tile), "r"(TILE_BYTES) : "memory");
        asm volatile("cp.async.bulk.commit_group;" ::: "memory");
        asm volatile("cp.async.bulk.wait_group 0;" ::: "memory");
    }
}

extern "C" void kernel_launch(void* const* d_in, const int* in_sizes, int n_in,
                              void* d_out, int out_size) {
    const float* reward = (const float*)d_in[0];   // batch_reward  [B] f32
    const float* dist   = (const float*)d_in[1];   // max_next_dist [B,51] f32
    // d_in[2] = supports (linspace) — folded into the affine map, unused
    const int*   mask   = (const int*)d_in[3];     // non_final_mask[B] i32
    float* out = (float*)d_out;                    // [B,51] f32

    const int B = in_sizes[0];                     // 1048576 (divisible by 64)
    const int blocks = B / ROWS;
    c51_project_kernel<<<blocks, THREADS>>>(reward, dist, mask, out);
}

// round 16
// speedup vs baseline: 1.0194x; 1.0133x over previous
#include <cuda_runtime.h>
#include <cstdint>

// C51 categorical projection, round 16 (final probe).
// R7 design verbatim (TMA bulk stage-in/out, 2 threads/row predicated
// streaming merge, in-place tile) + L2::cache_hint evict-first on both TMA
// directions: both streams are strictly single-touch, so evict-first lets
// LTS drop consumed input lines immediately and issue output writebacks
// eagerly, smoothing the read/write interleave at the memory controller —
// the only layer the nine previous SM-side experiments could not reach.

static constexpr int ATOMS_C    = 51;
static constexpr int ROWS       = 64;               // rows per block
static constexpr int THREADS    = 128;              // 2 threads per row
static constexpr int TILE       = ROWS * ATOMS_C;   // 3264 floats
static constexpr int TILE_BYTES = TILE * 4;         // 13056 (multiple of 16)
static constexpr int HALFN      = 26;               // atoms per half (incl. dummy)

__global__ __launch_bounds__(THREADS) void c51_project_kernel(
    const float* __restrict__ g_reward,
    const float* __restrict__ g_dist,
    const int*   __restrict__ g_mask,
    float*       __restrict__ g_out)
{
    __shared__ alignas(128) float s_tile[TILE];
    __shared__ alignas(8)  unsigned long long s_mbar;

    const int tid  = threadIdx.x;
    const int row  = tid & (ROWS - 1);
    const int half = tid >> 6;                      // 0: atoms 0..25, 1: 25..50
    const long long base_g = (long long)blockIdx.x * TILE;

    const uint32_t u_tile = (uint32_t)__cvta_generic_to_shared(s_tile);
    const uint32_t u_mbar = (uint32_t)__cvta_generic_to_shared(&s_mbar);

    // ---- TMA bulk load: GMEM -> SMEM, evict-first (single-touch stream) ----
    if (tid == 0) {
        asm volatile("mbarrier.init.shared::cta.b64 [%0], 1;" :: "r"(u_mbar));
        asm volatile("fence.proxy.async.shared::cta;" ::: "memory");
    }
    __syncthreads();
    if (tid == 0) {
        unsigned long long pol;
        asm volatile("createpolicy.fractional.L2::evict_first.b64 %0, 1.0;"
                     : "=l"(pol));
        asm volatile("mbarrier.arrive.expect_tx.shared::cta.b64 _, [%0], %1;"
                     :: "r"(u_mbar), "r"(TILE_BYTES) : "memory");
        asm volatile(
            "cp.async.bulk.shared::cta.global.mbarrier::complete_tx::bytes"
            ".L2::cache_hint [%0], [%1], %2, [%3], %4;"
            :: "r"(u_tile), "l"(g_dist + base_g), "r"(TILE_BYTES), "r"(u_mbar),
               "l"(pol)
            : "memory");
    }

    // ---- Overlap with TMA: per-row affine bin map ----
    const int   r    = blockIdx.x * ROWS + row;
    const float rw   = __ldg(g_reward + r);
    const float mk   = (float)__ldg(g_mask + r);
    const float step = 0.99f * mk;
    float base = (rw + 10.0f) / 0.4f - 24.75f * mk;       // one div per row
    base = fmaf(step, (float)(half * 25), base);           // shift to atom 25*half
    const float HI = 49.999996f;                           // largest f32 < 50

    // ---- Wait for the tile (parity 0) ----
    {
        uint32_t done;
        asm volatile(
            "{\n\t.reg .pred p;\n\t"
            "mbarrier.try_wait.parity.shared::cta.b64 p, [%1], 0;\n\t"
            "selp.b32 %0, 1, 0, p;\n\t}"
            : "=r"(done) : "r"(u_mbar) : "memory");
        while (!done) {
            asm volatile(
                "{\n\t.reg .pred p;\n\t"
                "mbarrier.try_wait.parity.shared::cta.b64 p, [%1], 0, 0x989680;\n\t"
                "selp.b32 %0, 1, 0, p;\n\t}"
                : "=r"(done) : "r"(u_mbar) : "memory");
        }
    }

    // ---- Buffer own half-row into registers (conflict-free, stride 51) ----
    float d[HALFN];
    {
        const float* __restrict__ srow = s_tile + row * ATOMS_C + half * 25;
        #pragma unroll
        for (int j = 0; j < HALFN; ++j) d[j] = srow[j];
        if (half) d[0] = 0.0f;                     // dummy atom 25: zero weight
    }
    __syncthreads();                               // all reads before overwrite

    // ---- Cooperative zero of the tile (reused in-place as output) ----
    float4* s4 = reinterpret_cast<float4*>(s_tile);
    const float4 z4 = make_float4(0.f, 0.f, 0.f, 0.f);
    #pragma unroll
    for (int i = 0; i < (TILE / 4) / THREADS; ++i)      // 6 rounds of 128
        s4[i * THREADS + tid] = z4;
    {   // remainder: 816 = 6*128 + 48
        if (tid < 48) s4[6 * THREADS + tid] = z4;
    }
    __syncthreads();

    // ---- Streaming merge over this thread's 26 atoms ----
    float* __restrict__ orow = s_tile + row * ATOMS_C;

    float b    = fminf(fmaxf(base, 0.0f), HI);
    float curf = floorf(b);
    float* wptr = orow + (int)curf;                // single F2I per thread
    float acc1 = d[0] * (b - curf);                // half==1: d[0]=0 -> accs 0
    float acc0 = d[0] - acc1;

    #pragma unroll
    for (int j = 1; j < HALFN; ++j) {
        float bb = fmaf(step, (float)j, base);     // FFMA, imm multiplier
        bb = fminf(fmaxf(bb, 0.0f), HI);
        const float lfn = floorf(bb);              // independent per atom
        const float bm  = bb - lfn;
        const float wu  = d[j] * bm;
        const float wl  = d[j] - wu;               // d*(lf+1-b)
        const bool adv  = (lfn != curf);           // l steps by exactly 0/1
        if (adv) *wptr = acc0;                     // @P STS, converged
        const float a0 = adv ? acc1 : acc0;
        acc0 = a0 + wl;
        const float t  = acc1 + wu;
        acc1 = adv ? wu : t;
        wptr = adv ? (wptr + 1) : wptr;
        curf = lfn;
    }
    if (half) {                                    // B: plain final flush
        wptr[0] = acc0;                            // covers [cA, cB+1] once
        wptr[1] = acc1;
    }
    __syncthreads();
    if (!half) {                                   // A: deferred carry, RMW add
        wptr[0] += acc0;                           // bins [cA, cA+1], B's region
        wptr[1] += acc1;
    }

    // ---- TMA bulk store: SMEM -> GMEM, evict-first (eager writeback) ----
    asm volatile("fence.proxy.async.shared::cta;" ::: "memory");
    __syncthreads();
    if (tid == 0) {
        unsigned long long pol;
        asm volatile("createpolicy.fractional.L2::evict_first.b64 %0, 1.0;"
                     : "=l"(pol));
        asm volatile(
            "cp.async.bulk.global.shared::cta.bulk_group.L2::cache_hint "
            "[%0], [%1], %2, %3;"
            :: "l"(g_out + base_g), "r"(u_tile), "r"(TILE_BYTES), "l"(pol)
            : "memory");
        asm volatile("cp.async.bulk.commit_group;" ::: "memory");
        asm volatile("cp.async.bulk.wait_group 0;" ::: "memory");
    }
}

extern "C" void kernel_launch(void* const* d_in, const int* in_sizes, int n_in,
                              void* d_out, int out_size) {
    const float* reward = (const float*)d_in[0];   // batch_reward  [B] f32
    const float* dist   = (const float*)d_in[1];   // max_next_dist [B,51] f32
    // d_in[2] = supports (linspace) — folded into the affine map, unused
    const int*   mask   = (const int*)d_in[3];     // non_final_mask[B] i32
    float* out = (float*)d_out;                    // [B,51] f32

    const int B = in_sizes[0];                     // 1048576 (divisible by 64)
    const int blocks = B / ROWS;
    c51_project_kernel<<<blocks, THREADS>>>(reward, dist, mask, out);
}